// round 8
// baseline (speedup 1.0000x reference)
#include <cuda_runtime.h>
#include <cstdint>

// Problem constants
#define S_LEN    2048
#define DMODEL   1024
#define NHEADS   16
#define DK       64
#define BATCH    2
#define M_TOTAL  (BATCH * S_LEN)   // 4096

// Scratch (allocation-free rule: __device__ globals)
__device__ float g_q[BATCH * NHEADS * S_LEN * DK];     // (B,H,S,dk) tf32-rounded
__device__ float g_k[BATCH * NHEADS * S_LEN * DK];
__device__ float g_v[BATCH * NHEADS * S_LEN * DK];
__device__ float g_att[BATCH * S_LEN * DMODEL];        // (B,S,D) tf32-rounded
__device__ float g_round[8 * 1024 * 1024];             // rounded x + 4 weights

// ---------------------------------------------------------------------------
// Helpers
// ---------------------------------------------------------------------------
__device__ __forceinline__ uint32_t smem_u32(const void* p) {
    uint32_t a;
    asm("{ .reg .u64 t; cvta.to.shared.u64 t, %1; cvt.u32.u64 %0, t; }"
        : "=r"(a) : "l"(p));
    return a;
}

__device__ __forceinline__ void cp_async16(uint32_t s, const void* g) {
    asm volatile("cp.async.cg.shared.global [%0], [%1], 16;" :: "r"(s), "l"(g));
}
#define CP_COMMIT() asm volatile("cp.async.commit_group;" ::: "memory")
#define CP_WAIT(n)  asm volatile("cp.async.wait_group %0;" :: "n"(n) : "memory")

__device__ __forceinline__ float round_tf32(float v) {
    uint32_t u;
    asm("cvt.rna.tf32.f32 %0, %1;" : "=r"(u) : "f"(v));
    return __uint_as_float(u);
}

// D(16x8) += A(16x8,row) * B(8x8,col)  -- tf32, fp32 accum
__device__ __forceinline__ void mma_tf32(float* d,
                                         uint32_t a0, uint32_t a1, uint32_t a2, uint32_t a3,
                                         uint32_t b0, uint32_t b1) {
    asm volatile(
        "mma.sync.aligned.m16n8k8.row.col.f32.tf32.tf32.f32 "
        "{%0,%1,%2,%3}, {%4,%5,%6,%7}, {%8,%9}, {%0,%1,%2,%3};"
        : "+f"(d[0]), "+f"(d[1]), "+f"(d[2]), "+f"(d[3])
        : "r"(a0), "r"(a1), "r"(a2), "r"(a3), "r"(b0), "r"(b1));
}

// ldmatrix x4: one instr loads four 8x8-b16 tiles (= four 8x4-f32 tiles)
__device__ __forceinline__ void ldsm4(uint32_t* r, uint32_t addr) {
    asm volatile("ldmatrix.sync.aligned.m8n8.x4.shared.b16 {%0,%1,%2,%3}, [%4];"
        : "=r"(r[0]), "=r"(r[1]), "=r"(r[2]), "=r"(r[3]) : "r"(addr));
}

// ---------------------------------------------------------------------------
// Single fused tf32 rounding pass over x + 4 weights.
// ---------------------------------------------------------------------------
__global__ __launch_bounds__(256) void round_all_kernel(
    const float* __restrict__ x,
    const float* __restrict__ wq, const float* __restrict__ wk,
    const float* __restrict__ wv, const float* __restrict__ wo,
    float* __restrict__ xr,
    float* __restrict__ wqr, float* __restrict__ wkr,
    float* __restrict__ wvr, float* __restrict__ wor)
{
    const int bidx = blockIdx.x;
    const float* src;
    float* dst;
    int off;
    if (bidx < 4096) { src = x; dst = xr; off = bidx; }
    else {
        const int i = (bidx - 4096) >> 10;
        off = (bidx - 4096) & 1023;
        src = (i == 0) ? wq : (i == 1) ? wk : (i == 2) ? wv : wo;
        dst = (i == 0) ? wqr : (i == 1) ? wkr : (i == 2) ? wvr : wor;
    }
    const int idx = off * 256 + threadIdx.x;
    float4 v = ((const float4*)src)[idx];
    float4 o;
    o.x = round_tf32(v.x); o.y = round_tf32(v.y);
    o.z = round_tf32(v.z); o.w = round_tf32(v.w);
    ((float4*)dst)[idx] = o;
}

// ---------------------------------------------------------------------------
// tf32 mma.sync GEMM (unchanged from round 7): tile 256x128, warp 64x64,
// XOR-swizzled 3-stage cp.async, ldmatrix fragments.
// ---------------------------------------------------------------------------
#define GTM 256
#define GTN 128
#define A_STAGE_F (GTM * 32)                 // 8192 floats = 32KB
#define B_STAGE_F (GTN * 32)                 // 4096 floats = 16KB
#define STG_F     (A_STAGE_F + B_STAGE_F)    // 12288 floats = 48KB
#define GSTAGES   3
#define GEMM_SMEM (GSTAGES * STG_F * (int)sizeof(float))   // 147456

__global__ __launch_bounds__(256, 1) void gemm_tc_kernel(
    const float* __restrict__ A,
    const float* __restrict__ W0, const float* __restrict__ W1, const float* __restrict__ W2,
    float* __restrict__ C0, float* __restrict__ C1, float* __restrict__ C2,
    int scatter)
{
    const float* __restrict__ W = (blockIdx.z == 0) ? W0 : (blockIdx.z == 1) ? W1 : W2;
    float* __restrict__ C       = (blockIdx.z == 0) ? C0 : (blockIdx.z == 1) ? C1 : C2;

    extern __shared__ float sm[];

    const int tid  = threadIdx.x;
    const int wid  = tid >> 5;
    const int lane = tid & 31;
    const int g    = lane >> 2;          // 0..7 row group
    const int t    = lane & 3;           // 0..3 thread-in-group
    const int wm   = wid & 3;            // warp m index (64 rows each)
    const int wn   = wid >> 2;           // warp n index (64 cols each)
    const int nBase = blockIdx.x * GTN;
    const int mBase = blockIdx.y * GTM;

    float acc[4][8][4];
#pragma unroll
    for (int i = 0; i < 4; i++)
#pragma unroll
        for (int j = 0; j < 8; j++)
#pragma unroll
            for (int l = 0; l < 4; l++) acc[i][j][l] = 0.0f;

    const uint32_t smemA0 = smem_u32(sm);

    const int rowA = wm * 64 + (lane & 15);
    const int rowB = wn * 64 + (lane & 7) + ((lane >> 4) << 3);
    const int c4bitA = lane >> 4;
    const int c4bitB = (lane >> 3) & 1;
    const int lxor   = lane & 7;

    auto issue = [&](int c, int s) {
        const uint32_t st = smemA0 + (uint32_t)(s * STG_F) * 4u;
#pragma unroll
        for (int i = 0; i < 8; i++) {
            const int idx = tid + 256 * i;
            const int r = idx >> 3, c4 = idx & 7;
            const uint32_t off = (uint32_t)(r * 32 + (((c4 ^ (r & 7)) & 7) << 2)) * 4u;
            cp_async16(st + off, A + (size_t)(mBase + r) * DMODEL + c * 32 + c4 * 4);
        }
#pragma unroll
        for (int i = 0; i < 4; i++) {
            const int idx = tid + 256 * i;
            const int r = idx >> 3, c4 = idx & 7;
            const uint32_t off = (uint32_t)(r * 32 + (((c4 ^ (r & 7)) & 7) << 2)) * 4u;
            cp_async16(st + (uint32_t)A_STAGE_F * 4u + off,
                       W + (size_t)(nBase + r) * DMODEL + c * 32 + c4 * 4);
        }
    };

    issue(0, 0); CP_COMMIT();
    issue(1, 1); CP_COMMIT();

    const int NCHUNK = DMODEL / 32;   // 32
    for (int c = 0; c < NCHUNK; c++) {
        CP_WAIT(1);
        __syncthreads();
        if (c + 2 < NCHUNK) issue(c + 2, (c + 2) % GSTAGES);
        CP_COMMIT();

        const uint32_t Ast = smemA0 + (uint32_t)((c % GSTAGES) * STG_F) * 4u;
        const uint32_t Bst = Ast + (uint32_t)A_STAGE_F * 4u;

#pragma unroll
        for (int ks = 0; ks < 4; ks++) {
            const int xa = ((2 * ks + c4bitA) ^ lxor) & 7;
            const int xb = ((2 * ks + c4bitB) ^ lxor) & 7;

            uint32_t a[4][4];
#pragma unroll
            for (int mt = 0; mt < 4; mt++)
                ldsm4(a[mt], Ast + (uint32_t)((rowA + mt * 16) * 32 + xa * 4) * 4u);

            uint32_t b[4][4];
#pragma unroll
            for (int ntp = 0; ntp < 4; ntp++)
                ldsm4(b[ntp], Bst + (uint32_t)((rowB + ntp * 16) * 32 + xb * 4) * 4u);

#pragma unroll
            for (int mt = 0; mt < 4; mt++)
#pragma unroll
                for (int ntp = 0; ntp < 4; ntp++) {
                    mma_tf32(acc[mt][2 * ntp],     a[mt][0], a[mt][1], a[mt][2], a[mt][3],
                             b[ntp][0], b[ntp][1]);
                    mma_tf32(acc[mt][2 * ntp + 1], a[mt][0], a[mt][1], a[mt][2], a[mt][3],
                             b[ntp][2], b[ntp][3]);
                }
        }
    }

#pragma unroll
    for (int mt = 0; mt < 4; mt++) {
#pragma unroll
        for (int half = 0; half < 2; half++) {
            const int m = mBase + wm * 64 + mt * 16 + g + half * 8;
#pragma unroll
            for (int nt = 0; nt < 8; nt++) {
                const int n = nBase + wn * 64 + nt * 8 + 2 * t;
                float2 v;
                v.x = acc[mt][nt][half * 2 + 0];
                v.y = acc[mt][nt][half * 2 + 1];
                if (scatter) {
                    v.x = round_tf32(v.x); v.y = round_tf32(v.y);
                    const int b = m >> 11, s = m & 2047;
                    const int head = n >> 6, d0 = n & 63;
                    *(float2*)&C[(((size_t)((b << 4) + head) * S_LEN + s) * DK + d0)] = v;
                } else {
                    *(float2*)&C[(size_t)m * DMODEL + n] = v;
                }
            }
        }
    }
}

// ---------------------------------------------------------------------------
// Flash attention, restructured with GEMM-style fragment machinery:
//  - Q fragments persistent in registers (loaded once, pre-scaled by 1/8)
//  - K in XOR-swizzled 32-float panels; b-frags via ldmatrix.x4
//  - P staged per-warp in swizzled panels; a-frags via ldmatrix.x4
//  - V scalar LDS (conflict-free, transposed layout incompatible w/ ldmatrix)
// CTA: 256 thr (8 warps), Q block 256 rows (32/warp), kv tile 64, 2 stages.
// ---------------------------------------------------------------------------
#define KPAN_F  2048                  // K panel: 64 rows x 32 floats
#define KST_F   4096                  // K stage (2 panels)
#define VSTR    68
#define VST_F   (64 * VSTR)           // 4352
#define ASTG_F  (KST_F + VST_F)       // 8448 floats per stage
#define SP_OFF  (2 * ASTG_F)          // 16896
#define SPW_F   2048                  // per-warp P region (2 panels x 32x32)
#define ATTN_F  (SP_OFF + 8 * SPW_F)  // 33280 floats
#define ATTN_SMEM (ATTN_F * (int)sizeof(float))   // 133120 bytes

__global__ __launch_bounds__(256) void attn_kernel(
    const float* __restrict__ Q, const float* __restrict__ K,
    const float* __restrict__ V, float* __restrict__ Oatt)
{
    extern __shared__ float sm[];

    const int tid  = threadIdx.x;
    const int wid  = tid >> 5;
    const int lane = tid & 31;
    const int g    = lane >> 2;
    const int t    = lane & 3;
    const int qb   = blockIdx.x;            // 0..7  (256 rows each)
    const int bh   = blockIdx.y;            // 0..31
    const int b    = bh >> 4;
    const int h    = bh & 15;

    const uint32_t smemB = smem_u32(sm);
    const uint32_t spw   = smemB + (uint32_t)(SP_OFF + wid * SPW_F) * 4u;
    float* sPf = sm + SP_OFF + wid * SPW_F;

    // ---- Q fragments persistent in registers (pre-scaled by 1/sqrt(dk))
    uint32_t qa[2][8][4];
    {
        const float* Qg = Q + ((size_t)bh * S_LEN + qb * 256 + wid * 32) * DK;
#pragma unroll
        for (int mt = 0; mt < 2; mt++)
#pragma unroll
            for (int ks = 0; ks < 8; ks++) {
                const float* p = Qg + (mt * 16 + g) * DK + ks * 8 + t;
                qa[mt][ks][0] = __float_as_uint(p[0] * 0.125f);
                qa[mt][ks][1] = __float_as_uint(p[8 * DK] * 0.125f);
                qa[mt][ks][2] = __float_as_uint(p[4] * 0.125f);
                qa[mt][ks][3] = __float_as_uint(p[8 * DK + 4] * 0.125f);
            }
    }

    float o_[2][8][4];
#pragma unroll
    for (int mt = 0; mt < 2; mt++)
#pragma unroll
        for (int nt = 0; nt < 8; nt++)
#pragma unroll
            for (int l = 0; l < 4; l++) o_[mt][nt][l] = 0.0f;
    float mrow[2][2] = {{-1e30f, -1e30f}, {-1e30f, -1e30f}};
    float lrow[2][2] = {{0.0f, 0.0f}, {0.0f, 0.0f}};

    const float* Kg = K + (size_t)bh * S_LEN * DK;
    const float* Vg = V + (size_t)bh * S_LEN * DK;

    // K/V tile loader (K swizzled panels, V padded rows)
    auto issue = [&](int kv, int st) {
        const uint32_t stb = smemB + (uint32_t)(st * ASTG_F) * 4u;
        const float* kS = Kg + (size_t)kv * 64 * DK;
        const float* vS = Vg + (size_t)kv * 64 * DK;
#pragma unroll
        for (int i = 0; i < 4; i++) {
            const int idx = tid + 256 * i;        // 0..1023
            const int r = idx >> 4, c4 = idx & 15;
            const uint32_t koff =
                (uint32_t)((c4 >> 3) * KPAN_F + r * 32 + ((((c4 & 7) ^ (r & 7)) & 7) << 2)) * 4u;
            cp_async16(stb + koff, kS + r * DK + c4 * 4);
            const uint32_t voff = (uint32_t)(KST_F + r * VSTR + c4 * 4) * 4u;
            cp_async16(stb + voff, vS + r * DK + c4 * 4);
        }
    };

    issue(0, 0); CP_COMMIT();

    const int rB  = (lane & 7) + ((lane >> 4) << 3);   // + nt2*16
    const int cbB = (lane >> 3) & 1;
    const int cbA = lane >> 4;
    const int lx  = lane & 7;
    const int rowPbase = lane & 15;                    // + mt*16

    const int NKV = S_LEN / 64;   // 32
    for (int kv = 0; kv < NKV; kv++) {
        CP_WAIT(0);
        __syncthreads();
        if (kv + 1 < NKV) issue(kv + 1, (kv + 1) & 1);
        CP_COMMIT();

        const uint32_t Kst = smemB + (uint32_t)((kv & 1) * ASTG_F) * 4u;
        const float* sV = sm + (kv & 1) * ASTG_F + KST_F;

        // ---- scores S = (Q/8) K^T   (32 x 64 per warp)
        float s_[2][8][4];
#pragma unroll
        for (int mt = 0; mt < 2; mt++)
#pragma unroll
            for (int nt = 0; nt < 8; nt++)
#pragma unroll
                for (int l = 0; l < 4; l++) s_[mt][nt][l] = 0.0f;

#pragma unroll
        for (int ks = 0; ks < 8; ks++) {
            const uint32_t pan = (uint32_t)((ks >> 2) * KPAN_F) * 4u;
            const uint32_t sw  = (uint32_t)((((2 * (ks & 3) + cbB) ^ lx) & 7) << 2) * 4u;
            uint32_t bb[4][4];
#pragma unroll
            for (int nt2 = 0; nt2 < 4; nt2++)
                ldsm4(bb[nt2], Kst + pan + (uint32_t)((nt2 * 16 + rB) * 32) * 4u + sw);
#pragma unroll
            for (int nt2 = 0; nt2 < 4; nt2++) {
                mma_tf32(s_[0][2 * nt2],     qa[0][ks][0], qa[0][ks][1], qa[0][ks][2], qa[0][ks][3],
                         bb[nt2][0], bb[nt2][1]);
                mma_tf32(s_[0][2 * nt2 + 1], qa[0][ks][0], qa[0][ks][1], qa[0][ks][2], qa[0][ks][3],
                         bb[nt2][2], bb[nt2][3]);
                mma_tf32(s_[1][2 * nt2],     qa[1][ks][0], qa[1][ks][1], qa[1][ks][2], qa[1][ks][3],
                         bb[nt2][0], bb[nt2][1]);
                mma_tf32(s_[1][2 * nt2 + 1], qa[1][ks][0], qa[1][ks][1], qa[1][ks][2], qa[1][ks][3],
                         bb[nt2][2], bb[nt2][3]);
            }
        }

        // ---- online softmax per m-tile; store P into swizzled panels
#pragma unroll
        for (int mt = 0; mt < 2; mt++) {
            float mx0 = -1e30f, mx1 = -1e30f;
#pragma unroll
            for (int nt = 0; nt < 8; nt++) {
                mx0 = fmaxf(mx0, fmaxf(s_[mt][nt][0], s_[mt][nt][1]));
                mx1 = fmaxf(mx1, fmaxf(s_[mt][nt][2], s_[mt][nt][3]));
            }
            mx0 = fmaxf(mx0, __shfl_xor_sync(0xffffffffu, mx0, 1));
            mx0 = fmaxf(mx0, __shfl_xor_sync(0xffffffffu, mx0, 2));
            mx1 = fmaxf(mx1, __shfl_xor_sync(0xffffffffu, mx1, 1));
            mx1 = fmaxf(mx1, __shfl_xor_sync(0xffffffffu, mx1, 2));

            float mn0 = fmaxf(mrow[mt][0], mx0), mn1 = fmaxf(mrow[mt][1], mx1);
            float al0 = __expf(mrow[mt][0] - mn0), al1 = __expf(mrow[mt][1] - mn1);
            mrow[mt][0] = mn0; mrow[mt][1] = mn1;

            float s0 = 0.0f, s1 = 0.0f;
#pragma unroll
            for (int nt = 0; nt < 8; nt++) {
                s_[mt][nt][0] = __expf(s_[mt][nt][0] - mn0); s0 += s_[mt][nt][0];
                s_[mt][nt][1] = __expf(s_[mt][nt][1] - mn0); s0 += s_[mt][nt][1];
                s_[mt][nt][2] = __expf(s_[mt][nt][2] - mn1); s1 += s_[mt][nt][2];
                s_[mt][nt][3] = __expf(s_[mt][nt][3] - mn1); s1 += s_[mt][nt][3];
            }
            s0 += __shfl_xor_sync(0xffffffffu, s0, 1);
            s0 += __shfl_xor_sync(0xffffffffu, s0, 2);
            s1 += __shfl_xor_sync(0xffffffffu, s1, 1);
            s1 += __shfl_xor_sync(0xffffffffu, s1, 2);
            lrow[mt][0] = lrow[mt][0] * al0 + s0;
            lrow[mt][1] = lrow[mt][1] * al1 + s1;

#pragma unroll
            for (int nt = 0; nt < 8; nt++) {
                o_[mt][nt][0] *= al0; o_[mt][nt][1] *= al0;
                o_[mt][nt][2] *= al1; o_[mt][nt][3] *= al1;
            }

            // P store (tf32-rounded) into swizzled panels
#pragma unroll
            for (int nt = 0; nt < 8; nt++) {
                const int pan = nt >> 2;
                const int grp = 2 * (nt & 3) + (t >> 1);
                const int offw = (2 * t) & 3;
                const int r0 = mt * 16 + g;
                float* d0 = sPf + pan * 1024 + r0 * 32 + (((grp ^ g) & 7) << 2) + offw;
                float2 p01 = make_float2(round_tf32(s_[mt][nt][0]), round_tf32(s_[mt][nt][1]));
                float2 p23 = make_float2(round_tf32(s_[mt][nt][2]), round_tf32(s_[mt][nt][3]));
                *(float2*)d0          = p01;
                *(float2*)(d0 + 256)  = p23;      // row+8: +8*32 floats
            }
        }
        __syncwarp();

        // ---- O += P V  (P a-frags via ldmatrix, V scalar)
#pragma unroll
        for (int kt = 0; kt < 8; kt++) {
            const uint32_t swp = (uint32_t)((((2 * (kt & 3) + cbA) ^ lx) & 7) << 2) * 4u;
            const uint32_t panp = (uint32_t)((kt >> 2) * 1024) * 4u;
            uint32_t ap[2][4];
#pragma unroll
            for (int mt = 0; mt < 2; mt++)
                ldsm4(ap[mt], spw + panp + (uint32_t)((mt * 16 + rowPbase) * 32) * 4u + swp);
#pragma unroll
            for (int nt = 0; nt < 8; nt++) {
                const float* Vr = sV + (kt * 8 + t) * VSTR + nt * 8 + g;
                uint32_t b0 = __float_as_uint(Vr[0]);
                uint32_t b1 = __float_as_uint(Vr[4 * VSTR]);
                mma_tf32(o_[0][nt], ap[0][0], ap[0][1], ap[0][2], ap[0][3], b0, b1);
                mma_tf32(o_[1][nt], ap[1][0], ap[1][1], ap[1][2], ap[1][3], b0, b1);
            }
        }
        __syncwarp();
    }

    // ---- epilogue: normalize, round to tf32, write (B,S,D)
#pragma unroll
    for (int mt = 0; mt < 2; mt++) {
        const float inv0 = 1.0f / lrow[mt][0], inv1 = 1.0f / lrow[mt][1];
        const int row0 = qb * 256 + wid * 32 + mt * 16 + g;
#pragma unroll
        for (int nt = 0; nt < 8; nt++) {
            const int col = h * DK + nt * 8 + 2 * t;
            float2 v0, v1;
            v0.x = round_tf32(o_[mt][nt][0] * inv0); v0.y = round_tf32(o_[mt][nt][1] * inv0);
            v1.x = round_tf32(o_[mt][nt][2] * inv1); v1.y = round_tf32(o_[mt][nt][3] * inv1);
            *(float2*)&Oatt[((size_t)b * S_LEN + row0) * DMODEL + col]     = v0;
            *(float2*)&Oatt[((size_t)b * S_LEN + row0 + 8) * DMODEL + col] = v1;
        }
    }
}

// ---------------------------------------------------------------------------
extern "C" void kernel_launch(void* const* d_in, const int* in_sizes, int n_in,
                              void* d_out, int out_size)
{
    const float* x  = (const float*)d_in[0];
    const float* Wq = (const float*)d_in[1];
    const float* Wk = (const float*)d_in[2];
    const float* Wv = (const float*)d_in[3];
    const float* Wo = (const float*)d_in[4];
    float* out = (float*)d_out;

    float *qp, *kp, *vp, *attp, *rp;
    cudaGetSymbolAddress((void**)&qp,   g_q);
    cudaGetSymbolAddress((void**)&kp,   g_k);
    cudaGetSymbolAddress((void**)&vp,   g_v);
    cudaGetSymbolAddress((void**)&attp, g_att);
    cudaGetSymbolAddress((void**)&rp,   g_round);

    float* xr  = rp;
    float* wqr = rp + 4 * 1024 * 1024;
    float* wkr = rp + 5 * 1024 * 1024;
    float* wvr = rp + 6 * 1024 * 1024;
    float* wor = rp + 7 * 1024 * 1024;

    // 0) single fused tf32 rna pre-rounding of all GEMM inputs
    round_all_kernel<<<8192, 256>>>(x, Wq, Wk, Wv, Wo, xr, wqr, wkr, wvr, wor);

    cudaFuncSetAttribute(gemm_tc_kernel, cudaFuncAttributeMaxDynamicSharedMemorySize,
                         GEMM_SMEM);
    cudaFuncSetAttribute(attn_kernel, cudaFuncAttributeMaxDynamicSharedMemorySize,
                         ATTN_SMEM);

    // 1) Fused QKV projections (tf32 mma), scatter+round to (B,H,S,dk)
    dim3 gQKV(DMODEL / GTN, M_TOTAL / GTM, 3);
    gemm_tc_kernel<<<gQKV, 256, GEMM_SMEM>>>(xr, wqr, wkr, wvr, qp, kp, vp, 1);

    // 2) Flash attention (tf32 mma) -> (B,S,D), rounded
    dim3 gA(S_LEN / 256, BATCH * NHEADS);
    attn_kernel<<<gA, 256, ATTN_SMEM>>>(qp, kp, vp, attp);

    // 3) Output projection (tf32 mma) -> d_out
    dim3 gO(DMODEL / GTN, M_TOTAL / GTM, 1);
    gemm_tc_kernel<<<gO, 256, GEMM_SMEM>>>(attp, wor, wor, wor, out, out, out, 0);
}